// round 17
// baseline (speedup 1.0000x reference)
#include <cuda_runtime.h>
#include <cuda_fp16.h>
#include <cstdint>

#define MAXN 100000
#define MAXE 1600000
#define DIN  64

// ---------------- scratch (no cudaMalloc allowed) ----------------
__device__ __half g_Xh[(size_t)MAXN * 64];   // fp16 copy of input x
__device__ __half g_HAh[(size_t)MAXN * 64];  // relu(layer1 out), fp16
__device__ __half g_HBh[(size_t)MAXN * 64];  // relu(layer2 out), fp16
__device__ float  g_PQ3[(size_t)MAXN * 8];   // layer3 P|Q per node (fp32)
__device__ int    g_counts[MAXN];
__device__ int    g_off[MAXN + 1];
__device__ int    g_cursor[MAXN];
__device__ int    g_bsum[64];
__device__ int    g_boff[64];
__device__ int2   g_meta[MAXE];              // {src, bits(e)} grouped by dst

// pre-transposed fp16 weights for layers 1-2: [mat 0..5][n*HPAD + k]
#define HPAD 72
#define SWH  (64 * HPAD)                      /* 4608 halves per mat */
__device__ __half g_Wh[6 * SWH];

// =================================================================
// CSR build (R16 winner, unchanged)
// =================================================================
__global__ void zero_kernel(int* __restrict__ counts, int N)
{
    int i = blockIdx.x * blockDim.x + threadIdx.x;
    if (i < N) counts[i] = 0;
}

__global__ void hist_kernel(const int* __restrict__ ei, int* __restrict__ counts, int E)
{
    int i = blockIdx.x * blockDim.x + threadIdx.x;
    int base = i * 4;
    if (base >= E) return;
    if (((E & 3) == 0) && (base + 4 <= E)) {
        int4 d = *reinterpret_cast<const int4*>(ei + E + base);
        atomicAdd(&counts[d.x], 1);
        atomicAdd(&counts[d.y], 1);
        atomicAdd(&counts[d.z], 1);
        atomicAdd(&counts[d.w], 1);
    } else {
        int hi = min(base + 4, E);
        for (int e = base; e < hi; e++) atomicAdd(&counts[__ldg(ei + E + e)], 1);
    }
}

__global__ __launch_bounds__(256) void scanA_kernel(const int* __restrict__ counts,
                                                    int* __restrict__ bsum, int N)
{
    __shared__ int red[256];
    int tid = threadIdx.x;
    int base = blockIdx.x * 2048 + tid * 8;
    int s = 0;
    if (base < N) {
        int4 a = *reinterpret_cast<const int4*>(counts + base);
        int4 b = *reinterpret_cast<const int4*>(counts + base + 4);
        s = a.x + a.y + a.z + a.w + b.x + b.y + b.z + b.w;
    }
    red[tid] = s;
    __syncthreads();
    #pragma unroll
    for (int d = 128; d > 0; d >>= 1) {
        if (tid < d) red[tid] += red[tid + d];
        __syncthreads();
    }
    if (tid == 0) bsum[blockIdx.x] = red[0];
}

__global__ __launch_bounds__(64) void scanB_kernel(const int* __restrict__ bsum,
                                                   int* __restrict__ boff,
                                                   int* __restrict__ off, int B, int N)
{
    __shared__ int sh[64];
    int tid = threadIdx.x;
    int v = (tid < B) ? bsum[tid] : 0;
    sh[tid] = v;
    __syncthreads();
    #pragma unroll
    for (int d = 1; d < 64; d <<= 1) {
        int t = (tid >= d) ? sh[tid - d] : 0;
        __syncthreads();
        sh[tid] += t;
        __syncthreads();
    }
    boff[tid] = sh[tid] - v;
    if (tid == 63) off[N] = sh[63];
}

__global__ __launch_bounds__(256) void scanC_kernel(const int* __restrict__ counts,
                                                    const int* __restrict__ boff,
                                                    int* __restrict__ off,
                                                    int* __restrict__ cursor, int N)
{
    __shared__ int wsum[8], woff[8];
    int tid = threadIdx.x;
    int lane = tid & 31;
    int warp = tid >> 5;
    int base = blockIdx.x * 2048 + tid * 8;

    int4 a = make_int4(0, 0, 0, 0), b = make_int4(0, 0, 0, 0);
    if (base < N) {
        a = *reinterpret_cast<const int4*>(counts + base);
        b = *reinterpret_cast<const int4*>(counts + base + 4);
    }
    int s = a.x + a.y + a.z + a.w + b.x + b.y + b.z + b.w;

    int incl = s;
    #pragma unroll
    for (int d = 1; d < 32; d <<= 1) {
        int t = __shfl_up_sync(0xFFFFFFFFu, incl, d);
        if (lane >= d) incl += t;
    }
    if (lane == 31) wsum[warp] = incl;
    __syncthreads();
    if (tid == 0) {
        int run = 0;
        #pragma unroll
        for (int j = 0; j < 8; j++) { int t = wsum[j]; woff[j] = run; run += t; }
    }
    __syncthreads();

    int ex = __ldg(boff + blockIdx.x) + woff[warp] + (incl - s);
    if (base < N) {
        int o0 = ex;
        int o1 = o0 + a.x, o2 = o1 + a.y, o3 = o2 + a.z, o4 = o3 + a.w;
        int o5 = o4 + b.x, o6 = o5 + b.y, o7 = o6 + b.z;
        int4 oa = make_int4(o0, o1, o2, o3);
        int4 ob = make_int4(o4, o5, o6, o7);
        *reinterpret_cast<int4*>(off + base)        = oa;
        *reinterpret_cast<int4*>(off + base + 4)    = ob;
        *reinterpret_cast<int4*>(cursor + base)     = oa;
        *reinterpret_cast<int4*>(cursor + base + 4) = ob;
    }
}

__global__ void scatter_kernel(const int* __restrict__ ei, const float* __restrict__ ea,
                               int* __restrict__ cursor, int2* __restrict__ meta, int E)
{
    int i = blockIdx.x * blockDim.x + threadIdx.x;
    int base = i * 4;
    if (base >= E) return;
    if (((E & 3) == 0) && (base + 4 <= E)) {
        int4 s4 = *reinterpret_cast<const int4*>(ei + base);
        int4 d4 = *reinterpret_cast<const int4*>(ei + E + base);
        float4 e4 = *reinterpret_cast<const float4*>(ea + base);
        int p0 = atomicAdd(&cursor[d4.x], 1);
        int p1 = atomicAdd(&cursor[d4.y], 1);
        int p2 = atomicAdd(&cursor[d4.z], 1);
        int p3 = atomicAdd(&cursor[d4.w], 1);
        meta[p0] = make_int2(s4.x, __float_as_int(e4.x));
        meta[p1] = make_int2(s4.y, __float_as_int(e4.y));
        meta[p2] = make_int2(s4.z, __float_as_int(e4.z));
        meta[p3] = make_int2(s4.w, __float_as_int(e4.w));
    } else {
        int hi = min(base + 4, E);
        for (int e = base; e < hi; e++) {
            int s = __ldg(ei + e);
            int d = __ldg(ei + E + e);
            int pos = atomicAdd(&cursor[d], 1);
            meta[pos] = make_int2(s, __float_as_int(__ldg(ea + e)));
        }
    }
}

// =================================================================
// Weight pre-transpose to fp16 (unchanged)
// =================================================================
__global__ __launch_bounds__(256) void pretrans_h_kernel(
    const float* __restrict__ m0, const float* __restrict__ m1, const float* __restrict__ m2,
    const float* __restrict__ m3, const float* __restrict__ m4, const float* __restrict__ m5,
    __half* __restrict__ out)
{
    int idx = blockIdx.x * blockDim.x + threadIdx.x;
    if (idx >= 6 * 4096) return;
    int mat = idx >> 12;
    int j = idx & 4095;
    int k = j >> 6;
    int n = j & 63;

    const float* src;
    switch (mat) {
        case 0: src = m0; break; case 1: src = m1; break; case 2: src = m2; break;
        case 3: src = m3; break; case 4: src = m4; break; default: src = m5; break;
    }
    out[(size_t)mat * SWH + n * HPAD + k] = __float2half_rn(__ldg(src + j));
}

// =================================================================
// x -> fp16 conversion (unchanged)
// =================================================================
__global__ __launch_bounds__(256) void cvt_half_kernel(const float* __restrict__ X,
                                                       __half* __restrict__ Xh, int total)
{
    int i = blockIdx.x * blockDim.x + threadIdx.x;
    int base = i * 8;
    if (base >= total) return;
    float4 a = *reinterpret_cast<const float4*>(X + base);
    float4 b = *reinterpret_cast<const float4*>(X + base + 4);
    __half2 h[4];
    h[0] = __float22half2_rn(make_float2(a.x, a.y));
    h[1] = __float22half2_rn(make_float2(a.z, a.w));
    h[2] = __float22half2_rn(make_float2(b.x, b.y));
    h[3] = __float22half2_rn(make_float2(b.z, b.w));
    *reinterpret_cast<uint4*>(Xh + base) = *reinterpret_cast<uint4*>(h);
}

// =================================================================
// FUSED agg + fp16 HMMA GEMM per layer:
// phase 1: 8 warps gather 16 nodes each (R11 loop) -> smem A tiles
// phase 2: H = relu(XE@Wm + X1@Bm + X@Wr + b) via m16n8k16 HMMA
// smem: sXE + sX1 + sX (128x72 halves each) + sW (64x72) = 64512 B
// =================================================================
#define SAH (128 * HPAD)                      /* 9216 halves */
#define FUSED_SMEM_BYTES ((3 * SAH + SWH) * 2)   /* 64512 B */

__device__ __forceinline__ void mma_f16(float* c, const uint32_t* a, const uint32_t* b)
{
    asm("mma.sync.aligned.m16n8k16.row.col.f32.f16.f16.f32 "
        "{%0,%1,%2,%3}, {%4,%5,%6,%7}, {%8,%9}, {%0,%1,%2,%3};"
        : "+f"(c[0]), "+f"(c[1]), "+f"(c[2]), "+f"(c[3])
        : "r"(a[0]), "r"(a[1]), "r"(a[2]), "r"(a[3]), "r"(b[0]), "r"(b[1]));
}

__global__ __launch_bounds__(256, 3) void fused_layer(const int* __restrict__ off,
                                                      const int2* __restrict__ meta,
                                                      const __half* __restrict__ Xh,
                                                      const __half* __restrict__ Wh,
                                                      const float* __restrict__ bias,
                                                      __half* __restrict__ Hh, int N)
{
    extern __shared__ __half smh[];
    __half* sXE = smh;                     // [row*HPAD + k]
    __half* sX1 = smh + SAH;
    __half* sX  = smh + 2 * SAH;
    __half* sW  = smh + 3 * SAH;           // [n*HPAD + k], one seg at a time

    const int tid  = threadIdx.x;
    const int lane = tid & 31;
    const int wid  = tid >> 5;
    const int grp  = lane >> 2;
    const int qid  = lane & 3;
    const int wm   = wid & 3;
    const int wn   = wid >> 2;
    const int row0 = blockIdx.x * 128;

    const __half2* X2 = reinterpret_cast<const __half2*>(Xh);

    // ---- phase 1a: gather (warp per node, 16 nodes per warp) ----
    #pragma unroll 1
    for (int i = 0; i < 16; i++) {
        int local = wid * 16 + i;
        int w = row0 + local;

        float2 aE = make_float2(0.f, 0.f);
        float2 a1 = make_float2(0.f, 0.f);

        if (w < N) {
            int beg = __ldg(off + w);
            int end = __ldg(off + w + 1);
            int k = beg;
            for (; k + 2 <= end; k += 2) {
                int2 m0 = __ldg(meta + k);
                int2 m1 = __ldg(meta + k + 1);
                float2 v0 = __half22float2(X2[(size_t)m0.x * 32 + lane]);
                float2 v1 = __half22float2(X2[(size_t)m1.x * 32 + lane]);
                float e0 = __int_as_float(m0.y);
                float e1 = __int_as_float(m1.y);
                aE.x = fmaf(e0, v0.x, aE.x); aE.y = fmaf(e0, v0.y, aE.y);
                aE.x = fmaf(e1, v1.x, aE.x); aE.y = fmaf(e1, v1.y, aE.y);
                a1.x += v0.x + v1.x;         a1.y += v0.y + v1.y;
            }
            if (k < end) {
                int2 m0 = __ldg(meta + k);
                float2 v0 = __half22float2(X2[(size_t)m0.x * 32 + lane]);
                float e0 = __int_as_float(m0.y);
                aE.x = fmaf(e0, v0.x, aE.x); aE.y = fmaf(e0, v0.y, aE.y);
                a1.x += v0.x;                a1.y += v0.y;
            }
        }
        reinterpret_cast<__half2*>(sXE + local * HPAD)[lane] = __float22half2_rn(aE);
        reinterpret_cast<__half2*>(sX1 + local * HPAD)[lane] = __float22half2_rn(a1);
    }

    // ---- phase 1b: stage root X tile + seg0 weights ----
    #pragma unroll
    for (int i = tid; i < 1024; i += 256) {
        int r  = i >> 3;
        int k8 = (i & 7) * 8;
        int row = row0 + r;
        uint4 v = make_uint4(0u, 0u, 0u, 0u);
        if (row < N) v = *reinterpret_cast<const uint4*>(Xh + (size_t)row * 64 + k8);
        *reinterpret_cast<uint4*>(sX + r * HPAD + k8) = v;
    }
    for (int i = tid; i < 576; i += 256) {
        uint4 v = __ldg(reinterpret_cast<const uint4*>(Wh) + i);
        *reinterpret_cast<uint4*>(sW + i * 8) = v;
    }
    __syncthreads();

    // ---- phase 2: 3 segments of HMMA ----
    float c[2][4][4];
    #pragma unroll
    for (int mt = 0; mt < 2; mt++)
        #pragma unroll
        for (int nt = 0; nt < 4; nt++)
            #pragma unroll
            for (int j = 0; j < 4; j++) c[mt][nt][j] = 0.f;

    #pragma unroll
    for (int seg = 0; seg < 3; seg++) {
        const __half* sA = (seg == 0) ? sXE : (seg == 1) ? sX1 : sX;

        #pragma unroll
        for (int kst = 0; kst < 4; kst++) {
            const int k0 = kst * 16;

            uint32_t a[2][4];
            #pragma unroll
            for (int mt = 0; mt < 2; mt++) {
                const __half* pa = sA + (wm * 32 + mt * 16 + grp) * HPAD + k0 + 2 * qid;
                a[mt][0] = *reinterpret_cast<const uint32_t*>(pa);
                a[mt][1] = *reinterpret_cast<const uint32_t*>(pa + 8 * HPAD);
                a[mt][2] = *reinterpret_cast<const uint32_t*>(pa + 8);
                a[mt][3] = *reinterpret_cast<const uint32_t*>(pa + 8 * HPAD + 8);
            }
            uint32_t b[4][2];
            #pragma unroll
            for (int nt = 0; nt < 4; nt++) {
                const __half* pb = sW + (wn * 32 + nt * 8 + grp) * HPAD + k0 + 2 * qid;
                b[nt][0] = *reinterpret_cast<const uint32_t*>(pb);
                b[nt][1] = *reinterpret_cast<const uint32_t*>(pb + 8);
            }

            #pragma unroll
            for (int mt = 0; mt < 2; mt++)
                #pragma unroll
                for (int nt = 0; nt < 4; nt++)
                    mma_f16(c[mt][nt], a[mt], b[nt]);
        }

        if (seg < 2) {
            __syncthreads();   // all fragment loads of sW done
            const __half* Wseg = Wh + (size_t)(seg + 1) * SWH;
            for (int i = tid; i < 576; i += 256) {
                uint4 v = __ldg(reinterpret_cast<const uint4*>(Wseg) + i);
                *reinterpret_cast<uint4*>(sW + i * 8) = v;
            }
            __syncthreads();
        }
    }

    // ---- epilogue: bias + relu + fp16 store ----
    #pragma unroll
    for (int mt = 0; mt < 2; mt++) {
        int rbase = row0 + wm * 32 + mt * 16 + grp;
        #pragma unroll
        for (int nt = 0; nt < 4; nt++) {
            int col = wn * 32 + nt * 8 + 2 * qid;
            float2 b2 = __ldg(reinterpret_cast<const float2*>(bias + col));
            if (rbase < N) {
                float2 v = make_float2(fmaxf(c[mt][nt][0] + b2.x, 0.f),
                                       fmaxf(c[mt][nt][1] + b2.y, 0.f));
                *reinterpret_cast<__half2*>(Hh + (size_t)rbase * 64 + col) = __float22half2_rn(v);
            }
            if (rbase + 8 < N) {
                float2 v = make_float2(fmaxf(c[mt][nt][2] + b2.x, 0.f),
                                       fmaxf(c[mt][nt][3] + b2.y, 0.f));
                *reinterpret_cast<__half2*>(Hh + (size_t)(rbase + 8) * 64 + col) = __float22half2_rn(v);
            }
        }
    }
}

// =================================================================
// Layer 3 project-first (R15/R16 winner, unchanged)
// =================================================================
__global__ __launch_bounds__(256) void gemm3_pq(const __half* __restrict__ HBh,
                                                const float* __restrict__ Wm,
                                                const float* __restrict__ Bm,
                                                const float* __restrict__ Wr,
                                                const float* __restrict__ b,
                                                float* __restrict__ PQ3,
                                                float* __restrict__ OUT, int N)
{
    __shared__ float sw[768];
    int tid = threadIdx.x;
    if (tid < 256) { sw[tid] = Wm[tid]; sw[256 + tid] = Bm[tid]; sw[512 + tid] = Wr[tid]; }
    __syncthreads();

    int row = blockIdx.x * blockDim.x + tid;
    if (row >= N) return;

    float p[4] = {0,0,0,0}, q[4] = {0,0,0,0}, r[4] = {0,0,0,0};
    const uint4* hb4 = reinterpret_cast<const uint4*>(HBh + (size_t)row * 64);

    #pragma unroll
    for (int blk = 0; blk < 8; blk++) {
        uint4 hv = __ldg(hb4 + blk);
        float2 f0 = __half22float2(*reinterpret_cast<__half2*>(&hv.x));
        float2 f1 = __half22float2(*reinterpret_cast<__half2*>(&hv.y));
        float2 f2 = __half22float2(*reinterpret_cast<__half2*>(&hv.z));
        float2 f3 = __half22float2(*reinterpret_cast<__half2*>(&hv.w));
        float xs[8] = {f0.x, f0.y, f1.x, f1.y, f2.x, f2.y, f3.x, f3.y};
        #pragma unroll
        for (int j = 0; j < 8; j++) {
            int k = blk * 8 + j;
            #pragma unroll
            for (int c = 0; c < 4; c++) {
                p[c] = fmaf(xs[j], sw[k * 4 + c], p[c]);
                q[c] = fmaf(xs[j], sw[256 + k * 4 + c], q[c]);
                r[c] = fmaf(xs[j], sw[512 + k * 4 + c], r[c]);
            }
        }
    }

    float4* pq = reinterpret_cast<float4*>(PQ3 + (size_t)row * 8);
    pq[0] = make_float4(p[0], p[1], p[2], p[3]);
    pq[1] = make_float4(q[0], q[1], q[2], q[3]);
    float4 o;
    o.x = r[0] + __ldg(b + 0);
    o.y = r[1] + __ldg(b + 1);
    o.z = r[2] + __ldg(b + 2);
    o.w = r[3] + __ldg(b + 3);
    *reinterpret_cast<float4*>(OUT + (size_t)row * 4) = o;
}

__global__ __launch_bounds__(256) void agg3_ls(const int* __restrict__ off,
                                               const int2* __restrict__ meta,
                                               const float* __restrict__ PQ3,
                                               float* __restrict__ OUT, int N)
{
    int w = blockIdx.x * blockDim.x + threadIdx.x;
    if (w >= N) return;

    int beg = __ldg(off + w);
    int end = __ldg(off + w + 1);

    float acc[4] = {0.f, 0.f, 0.f, 0.f};

    int k = beg;
    for (; k + 2 <= end; k += 2) {
        int2 m0 = __ldg(meta + k);
        int2 m1 = __ldg(meta + k + 1);
        const float4* pq0 = reinterpret_cast<const float4*>(PQ3 + (size_t)m0.x * 8);
        const float4* pq1 = reinterpret_cast<const float4*>(PQ3 + (size_t)m1.x * 8);
        float4 p0 = __ldg(pq0);
        float4 q0 = __ldg(pq0 + 1);
        float4 p1 = __ldg(pq1);
        float4 q1 = __ldg(pq1 + 1);
        float e0 = __int_as_float(m0.y);
        float e1 = __int_as_float(m1.y);
        acc[0] += fmaf(e0, p0.x, q0.x) + fmaf(e1, p1.x, q1.x);
        acc[1] += fmaf(e0, p0.y, q0.y) + fmaf(e1, p1.y, q1.y);
        acc[2] += fmaf(e0, p0.z, q0.z) + fmaf(e1, p1.z, q1.z);
        acc[3] += fmaf(e0, p0.w, q0.w) + fmaf(e1, p1.w, q1.w);
    }
    if (k < end) {
        int2 m0 = __ldg(meta + k);
        const float4* pq0 = reinterpret_cast<const float4*>(PQ3 + (size_t)m0.x * 8);
        float4 p0 = __ldg(pq0);
        float4 q0 = __ldg(pq0 + 1);
        float e0 = __int_as_float(m0.y);
        acc[0] += fmaf(e0, p0.x, q0.x);
        acc[1] += fmaf(e0, p0.y, q0.y);
        acc[2] += fmaf(e0, p0.z, q0.z);
        acc[3] += fmaf(e0, p0.w, q0.w);
    }

    float4 base = *reinterpret_cast<float4*>(OUT + (size_t)w * 4);
    float v0 = base.x + acc[0];
    float v1 = base.y + acc[1];
    float v2 = base.z + acc[2];
    float v3 = base.w + acc[3];

    float m = fmaxf(fmaxf(v0, v1), fmaxf(v2, v3));
    float s = __expf(v0 - m) + __expf(v1 - m) + __expf(v2 - m) + __expf(v3 - m);
    float lse = m + __logf(s);

    float4 o;
    o.x = v0 - lse; o.y = v1 - lse; o.z = v2 - lse; o.w = v3 - lse;
    *reinterpret_cast<float4*>(OUT + (size_t)w * 4) = o;
}

// =================================================================
extern "C" void kernel_launch(void* const* d_in, const int* in_sizes, int n_in,
                              void* d_out, int out_size)
{
    const float* x   = (const float*)d_in[0];
    const int*   ei  = (const int*)  d_in[1];
    const float* ea  = (const float*)d_in[2];
    const float* We1 = (const float*)d_in[3];
    const float* be1 = (const float*)d_in[4];
    const float* Wr1 = (const float*)d_in[5];
    const float* b1  = (const float*)d_in[6];
    const float* We2 = (const float*)d_in[7];
    const float* be2 = (const float*)d_in[8];
    const float* Wr2 = (const float*)d_in[9];
    const float* b2  = (const float*)d_in[10];
    const float* We3 = (const float*)d_in[11];
    const float* be3 = (const float*)d_in[12];
    const float* Wr3 = (const float*)d_in[13];
    const float* b3  = (const float*)d_in[14];

    const int N = in_sizes[0] / DIN;
    const int E = in_sizes[2];

    float *PQ3, *OUT = (float*)d_out;
    __half *Xh, *HAh, *HBh, *Wh;
    int *counts, *off, *cursor, *bsum, *boff;
    int2 *meta;
    cudaGetSymbolAddress((void**)&Xh, g_Xh);
    cudaGetSymbolAddress((void**)&HAh, g_HAh);
    cudaGetSymbolAddress((void**)&HBh, g_HBh);
    cudaGetSymbolAddress((void**)&PQ3, g_PQ3);
    cudaGetSymbolAddress((void**)&Wh, g_Wh);
    cudaGetSymbolAddress((void**)&counts, g_counts);
    cudaGetSymbolAddress((void**)&off, g_off);
    cudaGetSymbolAddress((void**)&cursor, g_cursor);
    cudaGetSymbolAddress((void**)&bsum, g_bsum);
    cudaGetSymbolAddress((void**)&boff, g_boff);
    cudaGetSymbolAddress((void**)&meta, g_meta);

    cudaFuncSetAttribute(fused_layer, cudaFuncAttributeMaxDynamicSharedMemorySize, FUSED_SMEM_BYTES);

    const int edge4Grid = (E / 4 + 256) / 256;
    const int rowGrid   = (N + 255) / 256;
    const int tcGrid    = (N + 127) / 128;
    const int scanGrid  = (N + 2047) / 2048;
    const int cvtGrid   = (N * 64 / 8 + 255) / 256;

    // ---- CSR build + weight pre-transpose + x->fp16 ----
    zero_kernel<<<rowGrid, 256>>>(counts, N);
    hist_kernel<<<edge4Grid, 256>>>(ei, counts, E);
    scanA_kernel<<<scanGrid, 256>>>(counts, bsum, N);
    scanB_kernel<<<1, 64>>>(bsum, boff, off, scanGrid, N);
    scanC_kernel<<<scanGrid, 256>>>(counts, boff, off, cursor, N);
    scatter_kernel<<<edge4Grid, 256>>>(ei, ea, cursor, meta, E);
    pretrans_h_kernel<<<96, 256>>>(We1, be1, Wr1, We2, be2, Wr2, Wh);
    cvt_half_kernel<<<cvtGrid, 256>>>(x, Xh, N * 64);

    // ---- layer 1 (fused agg + gemm) ----
    fused_layer<<<tcGrid, 256, FUSED_SMEM_BYTES>>>(off, meta, Xh, Wh, b1, HAh, N);

    // ---- layer 2 (fused agg + gemm) ----
    fused_layer<<<tcGrid, 256, FUSED_SMEM_BYTES>>>(off, meta, HAh,
                                                   Wh + (size_t)3 * SWH, b2, HBh, N);

    // ---- layer 3: project-first (64->4), then 32B/edge aggregate ----
    gemm3_pq<<<rowGrid, 256>>>(HBh, We3, be3, Wr3, b3, PQ3, OUT, N);
    agg3_ls<<<rowGrid, 256>>>(off, meta, PQ3, OUT, N);
}